// round 7
// baseline (speedup 1.0000x reference)
#include <cuda_runtime.h>
#include <cuda_bf16.h>
#include <cstdint>

#define BATCH 2
#define NC 4096
#define NF 16384
#define CC 256
#define CF 128
#define CO 256
#define KTOT 384  // CC + CF
#define NBLKF (NF / 128)

// ---------------- scratch (device globals; no allocations allowed) ----------
__device__ float g_Yc[BATCH * CO * NC];   // Wc @ Fc : [B, Co, Nc]
__device__ int   g_idx[BATCH * NF];
__device__ float g_ps [BATCH * CO * NBLKF];
__device__ float g_pss[BATCH * CO * NBLKF];
__device__ float g_scale[CO];
__device__ float g_shift[CO];
// pre-split bf16 operands (same layouts as fp32 originals)
__device__ __nv_bfloat16 g_Whi[CO * KTOT];
__device__ __nv_bfloat16 g_Wlo[CO * KTOT];
__device__ __nv_bfloat16 g_Ffh[BATCH * CF * NF];
__device__ __nv_bfloat16 g_Ffl[BATCH * CF * NF];
__device__ __nv_bfloat16 g_Fch[BATCH * CC * NC];
__device__ __nv_bfloat16 g_Fcl[BATCH * CC * NC];

// ---------------- helpers ----------------------------------------------------
__device__ __forceinline__ uint32_t smem_u32(const void* p) {
    uint32_t a;
    asm("{ .reg .u64 t; cvta.to.shared.u64 t, %1; cvt.u32.u64 %0, t; }"
        : "=r"(a) : "l"(p));
    return a;
}
__device__ __forceinline__ void cp16(uint32_t dst, const void* src) {
    asm volatile("cp.async.cg.shared.global [%0], [%1], 16;"
                 :: "r"(dst), "l"(src));
}
#define CP_COMMIT() asm volatile("cp.async.commit_group;" ::: "memory")
#define CP_WAIT1()  asm volatile("cp.async.wait_group 1;" ::: "memory")
#define CP_WAIT0()  asm volatile("cp.async.wait_group 0;" ::: "memory")

__device__ __forceinline__ void ldsm4(uint32_t (&r)[4], uint32_t addr) {
    asm volatile("ldmatrix.sync.aligned.m8n8.x4.shared.b16 {%0,%1,%2,%3}, [%4];"
                 : "=r"(r[0]), "=r"(r[1]), "=r"(r[2]), "=r"(r[3]) : "r"(addr));
}
__device__ __forceinline__ void ldsm4t(uint32_t (&r)[4], uint32_t addr) {
    asm volatile("ldmatrix.sync.aligned.m8n8.x4.trans.shared.b16 {%0,%1,%2,%3}, [%4];"
                 : "=r"(r[0]), "=r"(r[1]), "=r"(r[2]), "=r"(r[3]) : "r"(addr));
}
__device__ __forceinline__ void mma16816(float (&d)[4], const uint32_t (&a)[4],
                                         uint32_t b0, uint32_t b1) {
    asm volatile(
        "mma.sync.aligned.m16n8k16.row.col.f32.bf16.bf16.f32 "
        "{%0,%1,%2,%3}, {%4,%5,%6,%7}, {%8,%9}, {%0,%1,%2,%3};"
        : "+f"(d[0]), "+f"(d[1]), "+f"(d[2]), "+f"(d[3])
        : "r"(a[0]), "r"(a[1]), "r"(a[2]), "r"(a[3]), "r"(b0), "r"(b1));
}

__device__ __forceinline__ void split2(float x0, float x1, uint32_t& hi, uint32_t& lo) {
    __nv_bfloat16 h0 = __float2bfloat16(x0);
    __nv_bfloat16 h1 = __float2bfloat16(x1);
    float r0 = x0 - __bfloat162float(h0);
    float r1 = x1 - __bfloat162float(h1);
    __nv_bfloat162 hh;
    hh.x = h0; hh.y = h1;
    __nv_bfloat162 ll;
    ll.x = __float2bfloat16(r0); ll.y = __float2bfloat16(r1);
    hi = *(uint32_t*)&hh;
    lo = *(uint32_t*)&ll;
}

// ============================================================================
// K0: split fp32 -> bf16 hi/lo (same layout). which: 0=W, 1=Ff, 2=Fc
// ============================================================================
__global__ void split_kernel(const float4* __restrict__ src, int which) {
    const int i = blockIdx.x * 256 + threadIdx.x;
    uint2* hi;
    uint2* lo;
    if (which == 0)      { hi = (uint2*)g_Whi; lo = (uint2*)g_Wlo; }
    else if (which == 1) { hi = (uint2*)g_Ffh; lo = (uint2*)g_Ffl; }
    else                 { hi = (uint2*)g_Fch; lo = (uint2*)g_Fcl; }
    float4 v = src[i];
    uint32_t h0, l0, h1, l1;
    split2(v.x, v.y, h0, l0);
    split2(v.z, v.w, h1, l1);
    hi[i] = make_uint2(h0, h1);
    lo[i] = make_uint2(l0, l1);
}

// ============================================================================
// K1: nearest coarse neighbor. min-of-4 with rare branchy index resolution.
// ============================================================================
__global__ void nn_kernel(const float* __restrict__ xyzc,
                          const float* __restrict__ xyzf) {
    __shared__ float4 sc[2048];
    const int b = blockIdx.y;
    const int f = blockIdx.x * 128 + threadIdx.x;
    const float* p = xyzf + ((size_t)b * NF + f) * 3;
    const float px = -2.0f * p[0];
    const float py = -2.0f * p[1];
    const float pz = -2.0f * p[2];
    float best = 3.4e38f;
    int bi = 0;
    const float* xb = xyzc + (size_t)b * NC * 3;
    for (int half = 0; half < 2; half++) {
        for (int j = threadIdx.x; j < 2048; j += 128) {
            const float* c = xb + (size_t)(half * 2048 + j) * 3;
            float x = c[0], y = c[1], z = c[2];
            sc[j] = make_float4(x, y, z, x * x + y * y + z * z);
        }
        __syncthreads();
        const int base = half * 2048;
#pragma unroll 2
        for (int j = 0; j < 2048; j += 4) {
            float4 c0 = sc[j];
            float4 c1 = sc[j + 1];
            float4 c2 = sc[j + 2];
            float4 c3 = sc[j + 3];
            float d0 = fmaf(pz, c0.z, fmaf(py, c0.y, fmaf(px, c0.x, c0.w)));
            float d1 = fmaf(pz, c1.z, fmaf(py, c1.y, fmaf(px, c1.x, c1.w)));
            float d2 = fmaf(pz, c2.z, fmaf(py, c2.y, fmaf(px, c2.x, c2.w)));
            float d3 = fmaf(pz, c3.z, fmaf(py, c3.y, fmaf(px, c3.x, c3.w)));
            float m = fminf(fminf(d0, d1), fminf(d2, d3));
            if (m < best) {  // rare taken; resolve first index inside
                best = m;
                int jj = (d0 == m) ? 0 : (d1 == m) ? 1 : (d2 == m) ? 2 : 3;
                bi = base + j + jj;
            }
        }
        __syncthreads();
    }
    g_idx[b * NF + f] = bi;
}

// ============================================================================
// HMMA bf16 split GEMM, cp.async 2-stage pipeline on pre-split bf16 operands.
// out[b,m,n] = sum_k W[m,WOFF+k] * F[b,k,n]; hi*hi + hi*lo + lo*hi in fp32.
// BM=BN=128, BK=32, 256 threads (8 warps, 4m x 2n), warp tile 32x64.
// GATHER: += g_Yc[b][m][idx[n]], write dout, fused BN partials. else -> g_Yc.
// ============================================================================
#define AROW 40     // A tile row stride (bf16 elems): 80 B
#define BROW 136    // B tile row stride (bf16 elems): 272 B
#define OFF_AH 0
#define OFF_AL 10240
#define OFF_BH 20480
#define OFF_BL 29184
#define BUFSZ 37888
#define OSTR 132
#define SMEM_BYTES (2 * BUFSZ)  // 75776; epilogue (67584) overlays

template <int N, int KDIM, int WOFF, bool GATHER>
__global__ __launch_bounds__(256) void hmma_gemm_kernel(float* __restrict__ dout) {
    extern __shared__ char smp[];
    const uint32_t sb = smem_u32(smp);
    __shared__ int sidx[128];
    constexpr int NCH = KDIM / 32;

    const int b = blockIdx.z;
    const int mBase = blockIdx.y * 128;
    const int nBase = blockIdx.x * 128;
    const int t = threadIdx.x;
    const int w = t >> 5;
    const int lid = t & 31;
    const int wm = (w >> 1) * 32;
    const int wn = (w & 1) * 64;

    if (GATHER && t < 128) sidx[t] = g_idx[b * NF + nBase + t];

    const __nv_bfloat16* Ahi = g_Whi;
    const __nv_bfloat16* Alo = g_Wlo;
    const __nv_bfloat16* Bhi = GATHER ? g_Ffh : g_Fch;
    const __nv_bfloat16* Blo = GATHER ? g_Ffl : g_Fcl;

    float c[2][8][4];
#pragma unroll
    for (int mt = 0; mt < 2; mt++)
#pragma unroll
        for (int nt = 0; nt < 8; nt++)
#pragma unroll
            for (int r = 0; r < 4; r++) c[mt][nt][r] = 0.f;

    const char* Abh = (const char*)(Ahi + (size_t)mBase * KTOT + WOFF);
    const char* Abl = (const char*)(Alo + (size_t)mBase * KTOT + WOFF);
    const char* Bbh = (const char*)(Bhi + ((size_t)b * KDIM) * N + nBase);
    const char* Bbl = (const char*)(Blo + ((size_t)b * KDIM) * N + nBase);

    // copy-chunk mappings (per thread: 2 A-chunk pairs + 2 B-chunk pairs)
    const int ar0 = t >> 2;            // A chunk p=0: row, col16
    const int ac0 = t & 3;
    const int br0 = t >> 4;            // B chunk p=0: k-row, col16
    const int bc0 = t & 15;

    // ldmatrix lane addresses
    const int a_row = (lid & 7) + ((lid >> 3) & 1) * 8;
    const int a_colb = (lid >> 4) * 8;
    const int b_row = (lid & 7) + ((lid >> 3) & 1) * 8;
    const int b_colb = (lid >> 4) * 8;

    // --- issue helper (stage s, k-offset k0)
    auto issue = [&](int s, int k0) {
        const uint32_t st = sb + s * BUFSZ;
#pragma unroll
        for (int p = 0; p < 2; p++) {
            const int row = ar0 + p * 64;
            const int col = ac0;
            cp16(st + OFF_AH + row * 80 + col * 16,
                 Abh + (size_t)row * (KTOT * 2) + k0 * 2 + col * 16);
            cp16(st + OFF_AL + row * 80 + col * 16,
                 Abl + (size_t)row * (KTOT * 2) + k0 * 2 + col * 16);
        }
#pragma unroll
        for (int p = 0; p < 2; p++) {
            const int k = br0 + p * 16;
            const int col = bc0;
            cp16(st + OFF_BH + k * 272 + col * 16,
                 Bbh + (size_t)(k0 + k) * (N * 2) + col * 16);
            cp16(st + OFF_BL + k * 272 + col * 16,
                 Bbl + (size_t)(k0 + k) * (N * 2) + col * 16);
        }
    };

    issue(0, 0);
    CP_COMMIT();

#pragma unroll
    for (int ck = 0; ck < NCH; ck++) {
        if (ck + 1 < NCH) {
            issue((ck + 1) & 1, (ck + 1) * 32);
            CP_COMMIT();
            CP_WAIT1();
        } else {
            CP_WAIT0();
        }
        __syncthreads();

        const uint32_t cb = sb + (ck & 1) * BUFSZ;
#pragma unroll
        for (int k16 = 0; k16 < 2; k16++) {
            uint32_t ah[2][4], al[2][4], bh[4][4], bl[4][4];
#pragma unroll
            for (int mt = 0; mt < 2; mt++) {
                uint32_t ad = cb + ((wm + mt * 16 + a_row) * AROW + k16 * 16 + a_colb) * 2;
                ldsm4(ah[mt], ad + OFF_AH);
                ldsm4(al[mt], ad + OFF_AL);
            }
#pragma unroll
            for (int ng = 0; ng < 4; ng++) {
                uint32_t bd = cb + ((k16 * 16 + b_row) * BROW + wn + ng * 16 + b_colb) * 2;
                ldsm4t(bh[ng], bd + OFF_BH);
                ldsm4t(bl[ng], bd + OFF_BL);
            }
#pragma unroll
            for (int mt = 0; mt < 2; mt++)
#pragma unroll
                for (int nt = 0; nt < 8; nt++) {
                    const int ng = nt >> 1;
                    const int pr = (nt & 1) * 2;
                    mma16816(c[mt][nt], ah[mt], bh[ng][pr], bh[ng][pr + 1]);
                    mma16816(c[mt][nt], ah[mt], bl[ng][pr], bl[ng][pr + 1]);
                    mma16816(c[mt][nt], al[mt], bh[ng][pr], bh[ng][pr + 1]);
                }
        }
        __syncthreads();
    }

    // ---- epilogue: accum -> smem [128][OSTR] -> coalesced global
    float* smOut = (float*)smp;
    {
        const int r_m = lid >> 2;
        const int cn = (lid & 3) * 2;
#pragma unroll
        for (int mt = 0; mt < 2; mt++)
#pragma unroll
            for (int nt = 0; nt < 8; nt++) {
                const int row = wm + mt * 16 + r_m;
                const int col = wn + nt * 8 + cn;
                *(float2*)&smOut[row * OSTR + col] =
                    make_float2(c[mt][nt][0], c[mt][nt][1]);
                *(float2*)&smOut[(row + 8) * OSTR + col] =
                    make_float2(c[mt][nt][2], c[mt][nt][3]);
            }
    }
    __syncthreads();

#pragma unroll 4
    for (int rr = 0; rr < 16; rr++) {
        const int r0 = w + rr * 8;
        const int m = mBase + r0;
        float4 v = *(float4*)&smOut[r0 * OSTR + lid * 4];
        if (GATHER) {
            const float* yc = g_Yc + ((size_t)b * CO + m) * NC;
            v.x += yc[sidx[lid * 4 + 0]];
            v.y += yc[sidx[lid * 4 + 1]];
            v.z += yc[sidx[lid * 4 + 2]];
            v.w += yc[sidx[lid * 4 + 3]];
            *(float4*)&dout[((size_t)b * CO + m) * NF + nBase + lid * 4] = v;
            float s = v.x + v.y + v.z + v.w;
            float ss = v.x * v.x + v.y * v.y + v.z * v.z + v.w * v.w;
#pragma unroll
            for (int off = 16; off > 0; off >>= 1) {
                s += __shfl_down_sync(0xffffffffu, s, off);
                ss += __shfl_down_sync(0xffffffffu, ss, off);
            }
            if (lid == 0) {
                g_ps [((size_t)b * CO + m) * NBLKF + blockIdx.x] = s;
                g_pss[((size_t)b * CO + m) * NBLKF + blockIdx.x] = ss;
            }
        } else {
            *(float4*)&g_Yc[((size_t)b * CO + m) * NC + nBase + lid * 4] = v;
        }
    }
}

// ============================================================================
// K4: finish BN stats from partials
// ============================================================================
__global__ void stats2_kernel(const float* __restrict__ gamma,
                              const float* __restrict__ beta) {
    const int o = blockIdx.x * 8 + (threadIdx.x >> 5);
    const int lane = threadIdx.x & 31;
    float s = 0.f, ss = 0.f;
#pragma unroll
    for (int j = 0; j < 8; j++) {
        int p = lane + j * 32;
        int b = p >> 7;
        int nblk = p & 127;
        size_t off = ((size_t)b * CO + o) * NBLKF + nblk;
        s += g_ps[off];
        ss += g_pss[off];
    }
#pragma unroll
    for (int off = 16; off > 0; off >>= 1) {
        s += __shfl_down_sync(0xffffffffu, s, off);
        ss += __shfl_down_sync(0xffffffffu, ss, off);
    }
    if (lane == 0) {
        const float invn = 1.0f / (BATCH * NF);
        float mean = s * invn;
        float var = ss * invn - mean * mean;
        var = fmaxf(var, 0.0f);
        float r = rsqrtf(var + 1e-5f);
        float sc = gamma[o] * r;
        g_scale[o] = sc;
        g_shift[o] = beta[o] - mean * sc;
    }
}

// ============================================================================
// K5: y = relu(y * scale + shift) in place
// ============================================================================
__global__ void norm_kernel(float* __restrict__ y) {
    const size_t i = (size_t)blockIdx.x * blockDim.x + threadIdx.x;
    const int o = (int)((i >> 12) & (CO - 1));
    const float sc = g_scale[o];
    const float sh = g_shift[o];
    float4 v = ((const float4*)y)[i];
    v.x = fmaxf(fmaf(v.x, sc, sh), 0.0f);
    v.y = fmaxf(fmaf(v.y, sc, sh), 0.0f);
    v.z = fmaxf(fmaf(v.z, sc, sh), 0.0f);
    v.w = fmaxf(fmaf(v.w, sc, sh), 0.0f);
    ((float4*)y)[i] = v;
}

// ============================================================================
extern "C" void kernel_launch(void* const* d_in, const int* in_sizes, int n_in,
                              void* d_out, int out_size) {
    const float* xyzc  = (const float*)d_in[0];  // [2, 4096, 3]
    const float* fc    = (const float*)d_in[1];  // [2, 256, 4096]
    const float* xyzf  = (const float*)d_in[2];  // [2, 16384, 3]
    const float* ff    = (const float*)d_in[3];  // [2, 128, 16384]
    const float* W     = (const float*)d_in[4];  // [256, 384]
    const float* gamma = (const float*)d_in[5];  // [256]
    const float* beta  = (const float*)d_in[6];  // [256]
    float* out = (float*)d_out;                  // [2, 256, 16384]

    (void)in_sizes; (void)n_in; (void)out_size;

    static bool attr_done = false;
    if (!attr_done) {
        cudaFuncSetAttribute(hmma_gemm_kernel<NC, CC, 0, false>,
                             cudaFuncAttributeMaxDynamicSharedMemorySize, SMEM_BYTES);
        cudaFuncSetAttribute(hmma_gemm_kernel<NF, CF, CC, true>,
                             cudaFuncAttributeMaxDynamicSharedMemorySize, SMEM_BYTES);
        attr_done = true;
    }

    // operand pre-split (fp32 -> bf16 hi/lo, same layouts)
    split_kernel<<<CO * KTOT / 1024, 256>>>((const float4*)W, 0);
    split_kernel<<<BATCH * CF * NF / 1024, 256>>>((const float4*)ff, 1);
    split_kernel<<<BATCH * CC * NC / 1024, 256>>>((const float4*)fc, 2);

    nn_kernel<<<dim3(NF / 128, BATCH), 128>>>(xyzc, xyzf);

    // Yc = Wc @ Fc
    hmma_gemm_kernel<NC, CC, 0, false>
        <<<dim3(NC / 128, CO / 128, BATCH), 256, SMEM_BYTES>>>(out);

    // y = Wf @ Ff + gather(Yc), fused BN partials
    hmma_gemm_kernel<NF, CF, CC, true>
        <<<dim3(NF / 128, CO / 128, BATCH), 256, SMEM_BYTES>>>(out);

    stats2_kernel<<<CO / 8, 256>>>(gamma, beta);
    norm_kernel<<<(BATCH * CO * NF / 4) / 256, 256>>>(out);
}

// round 9
// speedup vs baseline: 1.1030x; 1.1030x over previous
#include <cuda_runtime.h>
#include <cuda_bf16.h>
#include <cstdint>

#define BATCH 2
#define NC 4096
#define NF 16384
#define CC 256
#define CF 128
#define CO 256
#define KTOT 384  // CC + CF
#define NBLKF (NF / 128)

// NN split config
#define NN_PTS 512            // fine points per block
#define NN_CHK 512            // coarse points per chunk
#define NN_NCHUNK (NC / NN_CHK)  // 8

typedef unsigned long long u64;

// ---------------- scratch (device globals; no allocations allowed) ----------
__device__ float g_Yc[BATCH * CO * NC];   // Wc @ Fc : [B, Co, Nc]
__device__ int   g_idx[BATCH * NF];
__device__ u64   g_nn_part[BATCH * NN_NCHUNK * NF];
__device__ float g_ps [BATCH * CO * NBLKF];
__device__ float g_pss[BATCH * CO * NBLKF];
__device__ float g_scale[CO];
__device__ float g_shift[CO];
// pre-split bf16 operands (same layouts as fp32 originals)
__device__ __nv_bfloat16 g_Whi[CO * KTOT];
__device__ __nv_bfloat16 g_Wlo[CO * KTOT];
__device__ __nv_bfloat16 g_Ffh[BATCH * CF * NF];
__device__ __nv_bfloat16 g_Ffl[BATCH * CF * NF];
__device__ __nv_bfloat16 g_Fch[BATCH * CC * NC];
__device__ __nv_bfloat16 g_Fcl[BATCH * CC * NC];

// ---------------- helpers ----------------------------------------------------
__device__ __forceinline__ uint32_t smem_u32(const void* p) {
    uint32_t a;
    asm("{ .reg .u64 t; cvta.to.shared.u64 t, %1; cvt.u32.u64 %0, t; }"
        : "=r"(a) : "l"(p));
    return a;
}
__device__ __forceinline__ void cp16(uint32_t dst, const void* src) {
    asm volatile("cp.async.cg.shared.global [%0], [%1], 16;"
                 :: "r"(dst), "l"(src));
}
#define CP_COMMIT() asm volatile("cp.async.commit_group;" ::: "memory")
#define CP_WAIT1()  asm volatile("cp.async.wait_group 1;" ::: "memory")
#define CP_WAIT0()  asm volatile("cp.async.wait_group 0;" ::: "memory")

__device__ __forceinline__ void ldsm4(uint32_t (&r)[4], uint32_t addr) {
    asm volatile("ldmatrix.sync.aligned.m8n8.x4.shared.b16 {%0,%1,%2,%3}, [%4];"
                 : "=r"(r[0]), "=r"(r[1]), "=r"(r[2]), "=r"(r[3]) : "r"(addr));
}
__device__ __forceinline__ void ldsm4t(uint32_t (&r)[4], uint32_t addr) {
    asm volatile("ldmatrix.sync.aligned.m8n8.x4.trans.shared.b16 {%0,%1,%2,%3}, [%4];"
                 : "=r"(r[0]), "=r"(r[1]), "=r"(r[2]), "=r"(r[3]) : "r"(addr));
}
__device__ __forceinline__ void mma16816(float (&d)[4], const uint32_t (&a)[4],
                                         uint32_t b0, uint32_t b1) {
    asm volatile(
        "mma.sync.aligned.m16n8k16.row.col.f32.bf16.bf16.f32 "
        "{%0,%1,%2,%3}, {%4,%5,%6,%7}, {%8,%9}, {%0,%1,%2,%3};"
        : "+f"(d[0]), "+f"(d[1]), "+f"(d[2]), "+f"(d[3])
        : "r"(a[0]), "r"(a[1]), "r"(a[2]), "r"(a[3]), "r"(b0), "r"(b1));
}

__device__ __forceinline__ void split2(float x0, float x1, uint32_t& hi, uint32_t& lo) {
    __nv_bfloat16 h0 = __float2bfloat16(x0);
    __nv_bfloat16 h1 = __float2bfloat16(x1);
    float r0 = x0 - __bfloat162float(h0);
    float r1 = x1 - __bfloat162float(h1);
    __nv_bfloat162 hh;
    hh.x = h0; hh.y = h1;
    __nv_bfloat162 ll;
    ll.x = __float2bfloat16(r0); ll.y = __float2bfloat16(r1);
    hi = *(uint32_t*)&hh;
    lo = *(uint32_t*)&ll;
}

// monotone float -> orderable u32 (neg floats map below pos floats)
__device__ __forceinline__ uint32_t fkey(float d) {
    uint32_t u = __float_as_uint(d);
    return (u & 0x80000000u) ? ~u : (u | 0x80000000u);
}
__device__ __forceinline__ u64 packdi(float d, int idx) {
    return ((u64)fkey(d) << 32) | (uint32_t)idx;
}

// ============================================================================
// K0: split fp32 -> bf16 hi/lo (same layout). which: 0=W, 1=Ff, 2=Fc
// ============================================================================
__global__ void split_kernel(const float4* __restrict__ src, int which) {
    const int i = blockIdx.x * 256 + threadIdx.x;
    uint2* hi;
    uint2* lo;
    if (which == 0)      { hi = (uint2*)g_Whi; lo = (uint2*)g_Wlo; }
    else if (which == 1) { hi = (uint2*)g_Ffh; lo = (uint2*)g_Ffl; }
    else                 { hi = (uint2*)g_Fch; lo = (uint2*)g_Fcl; }
    float4 v = src[i];
    uint32_t h0, l0, h1, l1;
    split2(v.x, v.y, h0, l0);
    split2(v.z, v.w, h1, l1);
    hi[i] = make_uint2(h0, h1);
    lo[i] = make_uint2(l0, l1);
}

// ============================================================================
// K1a: NN partial argmin. grid (NF/NN_PTS, NN_NCHUNK, B), 256 threads.
// Each thread: 2 fine points vs one 512-pt coarse chunk in smem.
// d(p,c) = |c|^2 - 2 p.c  (same argmin as euclidean).
// ============================================================================
__global__ __launch_bounds__(256) void nn_part_kernel(
    const float* __restrict__ xyzc, const float* __restrict__ xyzf) {
    __shared__ float4 sc[NN_CHK];
    const int b = blockIdx.z;
    const int chunk = blockIdx.y;
    const int t = threadIdx.x;
    const int f0 = blockIdx.x * NN_PTS + t;
    const int f1 = f0 + 256;

    const float* p0 = xyzf + ((size_t)b * NF + f0) * 3;
    const float* p1 = xyzf + ((size_t)b * NF + f1) * 3;
    const float px0 = -2.0f * p0[0], py0 = -2.0f * p0[1], pz0 = -2.0f * p0[2];
    const float px1 = -2.0f * p1[0], py1 = -2.0f * p1[1], pz1 = -2.0f * p1[2];

    const float* xb = xyzc + ((size_t)b * NC + chunk * NN_CHK) * 3;
    for (int j = t; j < NN_CHK; j += 256) {
        const float* c = xb + (size_t)j * 3;
        float x = c[0], y = c[1], z = c[2];
        sc[j] = make_float4(x, y, z, x * x + y * y + z * z);
    }
    __syncthreads();

    float best0 = 3.4e38f, best1 = 3.4e38f;
    int bi0 = 0, bi1 = 0;

#pragma unroll 2
    for (int j = 0; j < NN_CHK; j += 4) {
        float4 c0 = sc[j];
        float4 c1 = sc[j + 1];
        float4 c2 = sc[j + 2];
        float4 c3 = sc[j + 3];
        // point 0
        float d00 = fmaf(pz0, c0.z, fmaf(py0, c0.y, fmaf(px0, c0.x, c0.w)));
        float d01 = fmaf(pz0, c1.z, fmaf(py0, c1.y, fmaf(px0, c1.x, c1.w)));
        float d02 = fmaf(pz0, c2.z, fmaf(py0, c2.y, fmaf(px0, c2.x, c2.w)));
        float d03 = fmaf(pz0, c3.z, fmaf(py0, c3.y, fmaf(px0, c3.x, c3.w)));
        float m0 = fminf(fminf(d00, d01), fminf(d02, d03));
        if (m0 < best0) {
            best0 = m0;
            int jj = (d00 == m0) ? 0 : (d01 == m0) ? 1 : (d02 == m0) ? 2 : 3;
            bi0 = j + jj;
        }
        // point 1
        float d10 = fmaf(pz1, c0.z, fmaf(py1, c0.y, fmaf(px1, c0.x, c0.w)));
        float d11 = fmaf(pz1, c1.z, fmaf(py1, c1.y, fmaf(px1, c1.x, c1.w)));
        float d12 = fmaf(pz1, c2.z, fmaf(py1, c2.y, fmaf(px1, c2.x, c2.w)));
        float d13 = fmaf(pz1, c3.z, fmaf(py1, c3.y, fmaf(px1, c3.x, c3.w)));
        float m1 = fminf(fminf(d10, d11), fminf(d12, d13));
        if (m1 < best1) {
            best1 = m1;
            int jj = (d10 == m1) ? 0 : (d11 == m1) ? 1 : (d12 == m1) ? 2 : 3;
            bi1 = j + jj;
        }
    }

    const int cbase = chunk * NN_CHK;
    u64* part = g_nn_part + ((size_t)b * NN_NCHUNK + chunk) * NF;
    part[f0] = packdi(best0, cbase + bi0);
    part[f1] = packdi(best1, cbase + bi1);
}

// ============================================================================
// K1b: combine partials. u64-min over chunks (min dist, ties -> min idx).
// ============================================================================
__global__ void nn_combine_kernel() {
    const int i = blockIdx.x * 256 + threadIdx.x;  // over B*NF
    const int b = i >> 14;
    const int f = i & (NF - 1);
    const u64* part = g_nn_part + (size_t)b * NN_NCHUNK * NF + f;
    u64 best = part[0];
#pragma unroll
    for (int cshunk = 1; cshunk < NN_NCHUNK; cshunk++) {
        u64 v = part[(size_t)cshunk * NF];
        best = (v < best) ? v : best;
    }
    g_idx[i] = (int)(best & 0xFFFFFFFFu);
}

// ============================================================================
// HMMA bf16 split GEMM, cp.async 2-stage pipeline on pre-split bf16 operands.
// ============================================================================
#define AROW 40
#define BROW 136
#define OFF_AH 0
#define OFF_AL 10240
#define OFF_BH 20480
#define OFF_BL 29184
#define BUFSZ 37888
#define OSTR 132
#define SMEM_BYTES (2 * BUFSZ)

template <int N, int KDIM, int WOFF, bool GATHER>
__global__ __launch_bounds__(256) void hmma_gemm_kernel(float* __restrict__ dout) {
    extern __shared__ char smp[];
    const uint32_t sb = smem_u32(smp);
    __shared__ int sidx[128];
    constexpr int NCH = KDIM / 32;

    const int b = blockIdx.z;
    const int mBase = blockIdx.y * 128;
    const int nBase = blockIdx.x * 128;
    const int t = threadIdx.x;
    const int w = t >> 5;
    const int lid = t & 31;
    const int wm = (w >> 1) * 32;
    const int wn = (w & 1) * 64;

    if (GATHER && t < 128) sidx[t] = g_idx[b * NF + nBase + t];

    const __nv_bfloat16* Ahi = g_Whi;
    const __nv_bfloat16* Alo = g_Wlo;
    const __nv_bfloat16* Bhi = GATHER ? g_Ffh : g_Fch;
    const __nv_bfloat16* Blo = GATHER ? g_Ffl : g_Fcl;

    float c[2][8][4];
#pragma unroll
    for (int mt = 0; mt < 2; mt++)
#pragma unroll
        for (int nt = 0; nt < 8; nt++)
#pragma unroll
            for (int r = 0; r < 4; r++) c[mt][nt][r] = 0.f;

    const char* Abh = (const char*)(Ahi + (size_t)mBase * KTOT + WOFF);
    const char* Abl = (const char*)(Alo + (size_t)mBase * KTOT + WOFF);
    const char* Bbh = (const char*)(Bhi + ((size_t)b * KDIM) * N + nBase);
    const char* Bbl = (const char*)(Blo + ((size_t)b * KDIM) * N + nBase);

    const int ar0 = t >> 2;
    const int ac0 = t & 3;
    const int br0 = t >> 4;
    const int bc0 = t & 15;

    const int a_row = (lid & 7) + ((lid >> 3) & 1) * 8;
    const int a_colb = (lid >> 4) * 8;
    const int b_row = (lid & 7) + ((lid >> 3) & 1) * 8;
    const int b_colb = (lid >> 4) * 8;

    auto issue = [&](int s, int k0) {
        const uint32_t st = sb + s * BUFSZ;
#pragma unroll
        for (int p = 0; p < 2; p++) {
            const int row = ar0 + p * 64;
            const int col = ac0;
            cp16(st + OFF_AH + row * 80 + col * 16,
                 Abh + (size_t)row * (KTOT * 2) + k0 * 2 + col * 16);
            cp16(st + OFF_AL + row * 80 + col * 16,
                 Abl + (size_t)row * (KTOT * 2) + k0 * 2 + col * 16);
        }
#pragma unroll
        for (int p = 0; p < 2; p++) {
            const int k = br0 + p * 16;
            const int col = bc0;
            cp16(st + OFF_BH + k * 272 + col * 16,
                 Bbh + (size_t)(k0 + k) * (N * 2) + col * 16);
            cp16(st + OFF_BL + k * 272 + col * 16,
                 Bbl + (size_t)(k0 + k) * (N * 2) + col * 16);
        }
    };

    issue(0, 0);
    CP_COMMIT();

#pragma unroll
    for (int ck = 0; ck < NCH; ck++) {
        if (ck + 1 < NCH) {
            issue((ck + 1) & 1, (ck + 1) * 32);
            CP_COMMIT();
            CP_WAIT1();
        } else {
            CP_WAIT0();
        }
        __syncthreads();

        const uint32_t cb = sb + (ck & 1) * BUFSZ;
#pragma unroll
        for (int k16 = 0; k16 < 2; k16++) {
            uint32_t ah[2][4], al[2][4], bh[4][4], bl[4][4];
#pragma unroll
            for (int mt = 0; mt < 2; mt++) {
                uint32_t ad = cb + ((wm + mt * 16 + a_row) * AROW + k16 * 16 + a_colb) * 2;
                ldsm4(ah[mt], ad + OFF_AH);
                ldsm4(al[mt], ad + OFF_AL);
            }
#pragma unroll
            for (int ng = 0; ng < 4; ng++) {
                uint32_t bd = cb + ((k16 * 16 + b_row) * BROW + wn + ng * 16 + b_colb) * 2;
                ldsm4t(bh[ng], bd + OFF_BH);
                ldsm4t(bl[ng], bd + OFF_BL);
            }
#pragma unroll
            for (int mt = 0; mt < 2; mt++)
#pragma unroll
                for (int nt = 0; nt < 8; nt++) {
                    const int ng = nt >> 1;
                    const int pr = (nt & 1) * 2;
                    mma16816(c[mt][nt], ah[mt], bh[ng][pr], bh[ng][pr + 1]);
                    mma16816(c[mt][nt], ah[mt], bl[ng][pr], bl[ng][pr + 1]);
                    mma16816(c[mt][nt], al[mt], bh[ng][pr], bh[ng][pr + 1]);
                }
        }
        __syncthreads();
    }

    float* smOut = (float*)smp;
    {
        const int r_m = lid >> 2;
        const int cn = (lid & 3) * 2;
#pragma unroll
        for (int mt = 0; mt < 2; mt++)
#pragma unroll
            for (int nt = 0; nt < 8; nt++) {
                const int row = wm + mt * 16 + r_m;
                const int col = wn + nt * 8 + cn;
                *(float2*)&smOut[row * OSTR + col] =
                    make_float2(c[mt][nt][0], c[mt][nt][1]);
                *(float2*)&smOut[(row + 8) * OSTR + col] =
                    make_float2(c[mt][nt][2], c[mt][nt][3]);
            }
    }
    __syncthreads();

#pragma unroll 4
    for (int rr = 0; rr < 16; rr++) {
        const int r0 = w + rr * 8;
        const int m = mBase + r0;
        float4 v = *(float4*)&smOut[r0 * OSTR + lid * 4];
        if (GATHER) {
            const float* yc = g_Yc + ((size_t)b * CO + m) * NC;
            v.x += yc[sidx[lid * 4 + 0]];
            v.y += yc[sidx[lid * 4 + 1]];
            v.z += yc[sidx[lid * 4 + 2]];
            v.w += yc[sidx[lid * 4 + 3]];
            *(float4*)&dout[((size_t)b * CO + m) * NF + nBase + lid * 4] = v;
            float s = v.x + v.y + v.z + v.w;
            float ss = v.x * v.x + v.y * v.y + v.z * v.z + v.w * v.w;
#pragma unroll
            for (int off = 16; off > 0; off >>= 1) {
                s += __shfl_down_sync(0xffffffffu, s, off);
                ss += __shfl_down_sync(0xffffffffu, ss, off);
            }
            if (lid == 0) {
                g_ps [((size_t)b * CO + m) * NBLKF + blockIdx.x] = s;
                g_pss[((size_t)b * CO + m) * NBLKF + blockIdx.x] = ss;
            }
        } else {
            *(float4*)&g_Yc[((size_t)b * CO + m) * NC + nBase + lid * 4] = v;
        }
    }
}

// ============================================================================
// K4: finish BN stats from partials
// ============================================================================
__global__ void stats2_kernel(const float* __restrict__ gamma,
                              const float* __restrict__ beta) {
    const int o = blockIdx.x * 8 + (threadIdx.x >> 5);
    const int lane = threadIdx.x & 31;
    float s = 0.f, ss = 0.f;
#pragma unroll
    for (int j = 0; j < 8; j++) {
        int p = lane + j * 32;
        int b = p >> 7;
        int nblk = p & 127;
        size_t off = ((size_t)b * CO + o) * NBLKF + nblk;
        s += g_ps[off];
        ss += g_pss[off];
    }
#pragma unroll
    for (int off = 16; off > 0; off >>= 1) {
        s += __shfl_down_sync(0xffffffffu, s, off);
        ss += __shfl_down_sync(0xffffffffu, ss, off);
    }
    if (lane == 0) {
        const float invn = 1.0f / (BATCH * NF);
        float mean = s * invn;
        float var = ss * invn - mean * mean;
        var = fmaxf(var, 0.0f);
        float r = rsqrtf(var + 1e-5f);
        float sc = gamma[o] * r;
        g_scale[o] = sc;
        g_shift[o] = beta[o] - mean * sc;
    }
}

// ============================================================================
// K5: y = relu(y * scale + shift) in place
// ============================================================================
__global__ void norm_kernel(float* __restrict__ y) {
    const size_t i = (size_t)blockIdx.x * blockDim.x + threadIdx.x;
    const int o = (int)((i >> 12) & (CO - 1));
    const float sc = g_scale[o];
    const float sh = g_shift[o];
    float4 v = ((const float4*)y)[i];
    v.x = fmaxf(fmaf(v.x, sc, sh), 0.0f);
    v.y = fmaxf(fmaf(v.y, sc, sh), 0.0f);
    v.z = fmaxf(fmaf(v.z, sc, sh), 0.0f);
    v.w = fmaxf(fmaf(v.w, sc, sh), 0.0f);
    ((float4*)y)[i] = v;
}

// ============================================================================
extern "C" void kernel_launch(void* const* d_in, const int* in_sizes, int n_in,
                              void* d_out, int out_size) {
    const float* xyzc  = (const float*)d_in[0];  // [2, 4096, 3]
    const float* fc    = (const float*)d_in[1];  // [2, 256, 4096]
    const float* xyzf  = (const float*)d_in[2];  // [2, 16384, 3]
    const float* ff    = (const float*)d_in[3];  // [2, 128, 16384]
    const float* W     = (const float*)d_in[4];  // [256, 384]
    const float* gamma = (const float*)d_in[5];  // [256]
    const float* beta  = (const float*)d_in[6];  // [256]
    float* out = (float*)d_out;                  // [2, 256, 16384]

    (void)in_sizes; (void)n_in; (void)out_size;

    static bool attr_done = false;
    if (!attr_done) {
        cudaFuncSetAttribute(hmma_gemm_kernel<NC, CC, 0, false>,
                             cudaFuncAttributeMaxDynamicSharedMemorySize, SMEM_BYTES);
        cudaFuncSetAttribute(hmma_gemm_kernel<NF, CF, CC, true>,
                             cudaFuncAttributeMaxDynamicSharedMemorySize, SMEM_BYTES);
        attr_done = true;
    }

    // operand pre-split (fp32 -> bf16 hi/lo, same layouts)
    split_kernel<<<CO * KTOT / 1024, 256>>>((const float4*)W, 0);
    split_kernel<<<BATCH * CF * NF / 1024, 256>>>((const float4*)ff, 1);
    split_kernel<<<BATCH * CC * NC / 1024, 256>>>((const float4*)fc, 2);

    // NN: partial argmin over coarse chunks, then combine
    nn_part_kernel<<<dim3(NF / NN_PTS, NN_NCHUNK, BATCH), 256>>>(xyzc, xyzf);
    nn_combine_kernel<<<BATCH * NF / 256, 256>>>();

    // Yc = Wc @ Fc
    hmma_gemm_kernel<NC, CC, 0, false>
        <<<dim3(NC / 128, CO / 128, BATCH), 256, SMEM_BYTES>>>(out);

    // y = Wf @ Ff + gather(Yc), fused BN partials
    hmma_gemm_kernel<NF, CF, CC, true>
        <<<dim3(NF / 128, CO / 128, BATCH), 256, SMEM_BYTES>>>(out);

    stats2_kernel<<<CO / 8, 256>>>(gamma, beta);
    norm_kernel<<<(BATCH * CO * NF / 4) / 256, 256>>>(out);
}